// round 4
// baseline (speedup 1.0000x reference)
#include <cuda_runtime.h>
#include <math.h>

#define Bb 4
#define Nn 32
#define Mm 64
#define Kk 16
#define K1 17
#define Pp 128
#define Ww 128
#define TWd 256

typedef unsigned long long ull;

// ---------- f32x2 helpers ----------
__device__ __forceinline__ ull pack2(float a, float b) {
    ull r; asm("mov.b64 %0, {%1, %2};" : "=l"(r) : "f"(a), "f"(b)); return r;
}
__device__ __forceinline__ void unpack2(ull v, float& a, float& b) {
    asm("mov.b64 {%0, %1}, %2;" : "=f"(a), "=f"(b) : "l"(v));
}
__device__ __forceinline__ void fma2(ull& d, ull a, ull b) {
    asm("fma.rn.f32x2 %0, %1, %2, %0;" : "+l"(d) : "l"(a), "l"(b));
}
__device__ __forceinline__ ull add2(ull a, ull b) {
    ull r; asm("add.rn.f32x2 %0, %1, %2;" : "=l"(r) : "l"(a), "l"(b)); return r;
}
// exact identity tanh = 1 - 2/(exp(2x)+1); only error is __expf rounding (~2^-21)
__device__ __forceinline__ float ftanh(float x) {
    float e = __expf(2.0f * x);
    return 1.0f - __fdividef(2.0f, e + 1.0f);
}

// ------- scratch (device globals; no runtime allocation) -------
__device__ float d_A[Bb*Nn*K1*TWd];
__device__ float d_Bm[Bb*Mm*TWd];
__device__ float d_gdot[Bb*Nn*Mm];
// lane-duplicated weights
__device__ ulonglong2 d_tw1p[TWd*128];   // [j][t]: .x=dup(tw1[j][t]) .y=dup(tw1[j][t+128])
__device__ ulonglong2 d_tw2p[128*128];   // [j/2][t]: .x=dup(tw2[j][t]) .y=dup(tw2[j+1][t])
__device__ ull        d_sw0p[Ww*Ww];     // [i][w] dup
__device__ ull        d_sw1p[Ww*Ww];     // [i][w] dup

// =====================================================================
// K_dup: build duplicated weight arrays (runs every launch; ~5us)
// =====================================================================
__global__ void k_dup(const float* __restrict__ tw1, const float* __restrict__ tw2,
                      const float* __restrict__ sw0, const float* __restrict__ sw1)
{
    const int i = blockIdx.x*256 + threadIdx.x;   // grid 128*256 = 32768
    {   // tw1p
        const int j = i >> 7, t = i & 127;
        const float a = tw1[j*TWd + t], b = tw1[j*TWd + t + 128];
        d_tw1p[i] = make_ulonglong2(pack2(a,a), pack2(b,b));
    }
    if (i < 16384) {
        const int jp = i >> 7, t = i & 127;
        const float a = tw2[(2*jp)*Ww + t], b = tw2[(2*jp+1)*Ww + t];
        d_tw2p[i] = make_ulonglong2(pack2(a,a), pack2(b,b));
        const float c = sw0[i]; d_sw0p[i] = pack2(c,c);
        const float d = sw1[i]; d_sw1p[i] = pack2(d,d);
    }
}

// =====================================================================
// K1: attention MLP + softmax + coeff + A-partial.  One block per (b,n,k1).
// =====================================================================
__global__ void __launch_bounds__(128) k1_attn(
    const float* __restrict__ phase, const float* __restrict__ posc,
    const float* __restrict__ sigma, const float* __restrict__ velc,
    const float* __restrict__ aw0, const float* __restrict__ ab0,
    const float* __restrict__ aw1, const float* __restrict__ ab1,
    const float* __restrict__ aw2, const float* __restrict__ ab2,
    const float* __restrict__ tw0, const float* __restrict__ tb0)
{
    __shared__ float s_aw0[6*64];
    __shared__ float s_ab0[64];
    __shared__ float s_aw1[64*64];
    __shared__ float s_ab1[64];
    __shared__ float s_aw2[64];
    __shared__ float red[128];

    const int bx = blockIdx.x;
    const int k1 = bx % K1;
    const int n  = (bx / K1) % Nn;
    const int b  = bx / (K1*Nn);
    const int t  = threadIdx.x;

    for (int i = t; i < 6*64; i += 128) s_aw0[i] = aw0[i];
    if (t < 64) { s_ab0[t] = ab0[t]; s_aw2[t] = aw2[t]; s_ab1[t] = ab1[t]; }
    for (int i = t; i < 64*64; i += 128) s_aw1[i] = aw1[i];
    __syncthreads();

    const float x0 = phase[(b*Nn+n)*4 + 0];
    const float x1 = phase[(b*Nn+n)*4 + 1];
    float va0, va1;
    if (k1 == 0) { va0 = phase[(b*Nn+n)*4 + 2]; va1 = phase[(b*Nn+n)*4 + 3]; }
    else         { va0 = velc[(b*Kk + (k1-1))*2 + 0]; va1 = velc[(b*Kk + (k1-1))*2 + 1]; }
    const float inv = rsqrtf(va0*va0 + va1*va1 + 1e-16f);
    const float ag0 = va0*inv, ag1 = va1*inv;

    const float rx = x0 - posc[(b*Pp + t)*2 + 0];
    const float ry = x1 - posc[(b*Pp + t)*2 + 1];
    const float rd = sqrtf(rx*rx + ry*ry + 1e-16f);
    const float pl = rx*ag0 + ry*ag1;
    const float al = pl / (rd + 1e-8f);

    float h0[64];
#pragma unroll
    for (int j = 0; j < 64; j++) {
        h0[j] = ftanh(s_ab0[j] + x0*s_aw0[0*64+j] + x1*s_aw0[1*64+j]
                              + va0*s_aw0[2*64+j] + va1*s_aw0[3*64+j]
                              + al*s_aw0[4*64+j] + pl*s_aw0[5*64+j]);
    }
    float logit = ab2[0];
#pragma unroll
    for (int g = 0; g < 4; g++) {
        ull acc[8];
#pragma unroll
        for (int p = 0; p < 8; p++) acc[p] = 0ull;
        for (int j = 0; j < 64; j++) {
            const ull hp = pack2(h0[j], h0[j]);
            const float* wrow = &s_aw1[j*64 + g*16];
            ulonglong2 wA = *reinterpret_cast<const ulonglong2*>(wrow + 0);
            ulonglong2 wB = *reinterpret_cast<const ulonglong2*>(wrow + 4);
            ulonglong2 wC = *reinterpret_cast<const ulonglong2*>(wrow + 8);
            ulonglong2 wD = *reinterpret_cast<const ulonglong2*>(wrow + 12);
            fma2(acc[0], hp, wA.x); fma2(acc[1], hp, wA.y);
            fma2(acc[2], hp, wB.x); fma2(acc[3], hp, wB.y);
            fma2(acc[4], hp, wC.x); fma2(acc[5], hp, wC.y);
            fma2(acc[6], hp, wD.x); fma2(acc[7], hp, wD.y);
        }
#pragma unroll
        for (int p = 0; p < 8; p++) {
            const int i = g*16 + p*2;
            float a0, a1; unpack2(acc[p], a0, a1);
            logit += ftanh(a0 + s_ab1[i])   * s_aw2[i]
                   + ftanh(a1 + s_ab1[i+1]) * s_aw2[i+1];
        }
    }

    float lg = (pl > 0.0f) ? logit : -1e30f;
    red[t] = lg; __syncthreads();
    for (int s = 64; s > 0; s >>= 1) { if (t < s) red[t] = fmaxf(red[t], red[t+s]); __syncthreads(); }
    const float mx = red[0]; __syncthreads();
    const float e = __expf(lg - mx);
    red[t] = e; __syncthreads();
    for (int s = 64; s > 0; s >>= 1) { if (t < s) red[t] += red[t+s]; __syncthreads(); }
    const float denom = red[0]; __syncthreads();
    const float aw = e / denom;

    const float sg0 = sigma[(b*Pp+t)*2 + 0];
    const float sg1 = sigma[(b*Pp+t)*2 + 1];
    red[t] = aw*sg0; __syncthreads();
    for (int s = 64; s > 0; s >>= 1) { if (t < s) red[t] += red[t+s]; __syncthreads(); }
    const float sum0 = red[0]; __syncthreads();
    red[t] = aw*sg1; __syncthreads();
    for (int s = 64; s > 0; s >>= 1) { if (t < s) red[t] += red[t+s]; __syncthreads(); }
    const float sum1 = red[0]; __syncthreads();

    const float c0 = __expf(-sum0);
    const float c1 = __expf(-sum1);

    for (int tt = t; tt < TWd; tt += 128) {
        float a = tb0[tt]
                + x0*tw0[0*TWd+tt] + x1*tw0[1*TWd+tt]
                + va0*tw0[2*TWd+tt] + va1*tw0[3*TWd+tt]
                + c0*tw0[8*TWd+tt] + c1*tw0[9*TWd+tt];
        d_A[bx*TWd + tt] = a;
    }
}

// =====================================================================
__global__ void k_bm(const float* __restrict__ bcoords, const float* __restrict__ tw0)
{
    const int bm = blockIdx.x;
    const int t  = threadIdx.x;
    const float xp0 = bcoords[bm*4+0], xp1 = bcoords[bm*4+1];
    const float vp0 = bcoords[bm*4+2], vp1 = bcoords[bm*4+3];
    d_Bm[bm*TWd + t] = xp0*tw0[4*TWd+t] + xp1*tw0[5*TWd+t]
                     + vp0*tw0[6*TWd+t] + vp1*tw0[7*TWd+t];
}

// =====================================================================
// K4: transport MLP (layers 1,2) + scattering chain. One block per
// (b,n,m-pair), 128 threads, m's in f32x2 lanes, weights pre-duplicated.
// =====================================================================
__global__ void __launch_bounds__(128) k4_main(
    const float* __restrict__ scat, const float* __restrict__ sscat,
    const float* __restrict__ vwt,
    const float* __restrict__ tb1, const float* __restrict__ tb2,
    const float* __restrict__ sb0, const float* __restrict__ sb1,
    const float* __restrict__ out_w)
{
    __shared__ float buf[8704];      // h0(17x512) -> h1(17x512) -> [g(17x256)|rr(17x256)]
    __shared__ ull   ws2[272];
    __shared__ float sres[256];
    __shared__ float sred[8];

    const int bx   = blockIdx.x;
    const int pair = bx & 31;
    const int n    = (bx >> 5) & 31;
    const int b    = bx >> 10;
    const int t    = threadIdx.x;

    for (int i = t; i < 272; i += 128) {
        const int row = i >> 4, j = i & 15;
        float v = (row == 0) ? (1.0f - scat[(b*Nn+n)*Kk + j])
                             : (1.0f - sscat[b*256 + (row-1)*Kk + j]);
        v *= vwt[b*Kk + j];
        ws2[i] = pack2(v, v);
    }

    // ---- layer 0 ----
    const float* Arow = d_A + (b*Nn + n)*K1*TWd;
    const float* bm0  = d_Bm + (b*Mm + pair*2 + 0)*TWd;
    const float* bm1  = bm0 + TWd;
    {
        const float b0a = bm0[t], b0b = bm0[t+128];
        const float b1a = bm1[t], b1b = bm1[t+128];
#pragma unroll
        for (int k = 0; k < K1; k++) {
            const float A0 = Arow[k*TWd + t];
            const float A1 = Arow[k*TWd + t + 128];
            *reinterpret_cast<ull*>(buf + k*512 + 2*t) =
                pack2(ftanh(A0 + b0a), ftanh(A0 + b1a));
            *reinterpret_cast<ull*>(buf + k*512 + 2*(t+128)) =
                pack2(ftanh(A1 + b0b), ftanh(A1 + b1b));
        }
    }
    __syncthreads();

    // ---- layer 1: thread owns cols t and t+128; w pairs pre-duplicated ----
    {
        ull acc0[K1], acc1[K1];
#pragma unroll
        for (int k = 0; k < K1; k++) { acc0[k] = 0ull; acc1[k] = 0ull; }
        for (int j = 0; j < TWd; j += 4) {
            const ulonglong2 w0 = d_tw1p[(j+0)*128 + t];
            const ulonglong2 w1 = d_tw1p[(j+1)*128 + t];
            const ulonglong2 w2 = d_tw1p[(j+2)*128 + t];
            const ulonglong2 w3 = d_tw1p[(j+3)*128 + t];
#pragma unroll
            for (int k = 0; k < K1; k++) {
                ulonglong2 ha = *reinterpret_cast<const ulonglong2*>(buf + k*512 + j*2);
                ulonglong2 hb = *reinterpret_cast<const ulonglong2*>(buf + k*512 + j*2 + 4);
                fma2(acc0[k], ha.x, w0.x); fma2(acc1[k], ha.x, w0.y);
                fma2(acc0[k], ha.y, w1.x); fma2(acc1[k], ha.y, w1.y);
                fma2(acc0[k], hb.x, w2.x); fma2(acc1[k], hb.x, w2.y);
                fma2(acc0[k], hb.y, w3.x); fma2(acc1[k], hb.y, w3.y);
            }
        }
        __syncthreads();
        const float t1a = tb1[t], t1b = tb1[t+128];
#pragma unroll
        for (int k = 0; k < K1; k++) {
            float x0, x1; unpack2(acc0[k], x0, x1);
            float y0, y1; unpack2(acc1[k], y0, y1);
            *reinterpret_cast<ull*>(buf + k*512 + 2*t) =
                pack2(ftanh(x0+t1a), ftanh(x1+t1a));
            *reinterpret_cast<ull*>(buf + k*512 + 2*(t+128)) =
                pack2(ftanh(y0+t1b), ftanh(y1+t1b));
        }
        __syncthreads();
    }

    // ---- layer 2: thread = col t ----
    {
        ull acc[K1];
#pragma unroll
        for (int k = 0; k < K1; k++) acc[k] = 0ull;
        for (int j = 0; j < TWd; j += 4) {
            const int jp = j >> 1;
            const ulonglong2 wA = d_tw2p[jp*128 + t];       // j, j+1
            const ulonglong2 wB = d_tw2p[(jp+1)*128 + t];   // j+2, j+3
#pragma unroll
            for (int k = 0; k < K1; k++) {
                ulonglong2 ha = *reinterpret_cast<const ulonglong2*>(buf + k*512 + j*2);
                ulonglong2 hb = *reinterpret_cast<const ulonglong2*>(buf + k*512 + j*2 + 4);
                fma2(acc[k], ha.x, wA.x); fma2(acc[k], ha.y, wA.y);
                fma2(acc[k], hb.x, wB.x); fma2(acc[k], hb.y, wB.y);
            }
        }
        __syncthreads();
        const float tb2c = tb2[t];
#pragma unroll
        for (int k = 0; k < K1; k++) {
            float x0, x1; unpack2(acc[k], x0, x1);
            *reinterpret_cast<ull*>(buf + k*256 + 2*t) =
                pack2(__expf(ftanh(x0+tb2c)), __expf(ftanh(x1+tb2c)));
        }
        __syncthreads();
    }

    // ---- stage 1: rr from old g rows 1..16 ----
    {
        ull r[K1];
#pragma unroll
        for (int k = 0; k < K1; k++) r[k] = 0ull;
#pragma unroll
        for (int j = 0; j < Kk; j++) {
            const ull g2 = *reinterpret_cast<const ull*>(buf + (1+j)*256 + 2*t);
#pragma unroll
            for (int k = 0; k < K1; k++)
                fma2(r[k], g2, ws2[k*Kk + j]);
        }
#pragma unroll
        for (int k = 0; k < K1; k++)
            *reinterpret_cast<ull*>(buf + 4352 + k*256 + 2*t) = r[k];
        __syncthreads();
    }

    // ---- stage 2: g[row][t] += tanh(sw0[t][:] @ rr[row][:] + sb0[t]) ----
    {
        ull s2[K1];
#pragma unroll
        for (int k = 0; k < K1; k++) s2[k] = 0ull;
        const ull* swr = d_sw0p + t*Ww;
        for (int w = 0; w < Ww; w += 4) {
            const ulonglong2 sA = *reinterpret_cast<const ulonglong2*>(swr + w);     // w, w+1
            const ulonglong2 sB = *reinterpret_cast<const ulonglong2*>(swr + w + 2); // w+2, w+3
#pragma unroll
            for (int k = 0; k < K1; k++) {
                ulonglong2 ra = *reinterpret_cast<const ulonglong2*>(buf + 4352 + k*256 + w*2);
                ulonglong2 rb = *reinterpret_cast<const ulonglong2*>(buf + 4352 + k*256 + w*2 + 4);
                fma2(s2[k], ra.x, sA.x); fma2(s2[k], ra.y, sA.y);
                fma2(s2[k], rb.x, sB.x); fma2(s2[k], rb.y, sB.y);
            }
        }
        const float sb0c = sb0[t];
#pragma unroll
        for (int k = 0; k < K1; k++) {
            float a0, a1; unpack2(s2[k], a0, a1);
            ull* gp = reinterpret_cast<ull*>(buf + k*256 + 2*t);
            float g0, g1; unpack2(*gp, g0, g1);
            *gp = pack2(g0 + ftanh(a0+sb0c), g1 + ftanh(a1+sb0c));
        }
        __syncthreads();
    }

    // ---- stage 3: resv2 ----
    {
        ull rv = 0ull;
#pragma unroll
        for (int k = 0; k < Kk; k++)
            fma2(rv, *reinterpret_cast<const ull*>(buf + (1+k)*256 + 2*t), ws2[k]);
        *reinterpret_cast<ull*>(sres + 2*t) = rv;
    }
    __syncthreads();

    // ---- stage 4: green + gdot (warp-shuffle reduction) ----
    {
        ull sa = 0ull, sb = 0ull;
        const ull* sw1r = d_sw1p + t*Ww;
        for (int w = 0; w < Ww; w += 4) {
            const ulonglong2 vA = *reinterpret_cast<const ulonglong2*>(sw1r + w);
            const ulonglong2 vB = *reinterpret_cast<const ulonglong2*>(sw1r + w + 2);
            ulonglong2 ra = *reinterpret_cast<const ulonglong2*>(sres + w*2);
            ulonglong2 rb = *reinterpret_cast<const ulonglong2*>(sres + w*2 + 4);
            fma2(sa, ra.x, vA.x); fma2(sb, ra.y, vA.y);
            fma2(sa, rb.x, vB.x); fma2(sb, rb.y, vB.y);
        }
        const ull tot = add2(sa, sb);
        float a0, a1; unpack2(tot, a0, a1);
        float v0, v1; unpack2(*reinterpret_cast<const ull*>(buf + 2*t), v0, v1);
        const float sb1c = sb1[t], ow = out_w[t];
        float p0 = (v0 + ftanh(a0+sb1c)) * ow;
        float p1 = (v1 + ftanh(a1+sb1c)) * ow;
#pragma unroll
        for (int o = 16; o > 0; o >>= 1) {
            p0 += __shfl_down_sync(0xffffffffu, p0, o);
            p1 += __shfl_down_sync(0xffffffffu, p1, o);
        }
        if ((t & 31) == 0) { sred[(t>>5)*2] = p0; sred[(t>>5)*2+1] = p1; }
        __syncthreads();
        if (t == 0) {
            d_gdot[(b*Nn+n)*Mm + pair*2 + 0] = sred[0]+sred[2]+sred[4]+sred[6];
            d_gdot[(b*Nn+n)*Mm + pair*2 + 1] = sred[1]+sred[3]+sred[5]+sred[7];
        }
    }
}

// =====================================================================
__global__ void k6_final(const float* __restrict__ boundary,
                         const float* __restrict__ bweights,
                         float* __restrict__ out)
{
    __shared__ float s2[2];
    const int bn = blockIdx.x;
    const int b  = bn >> 5;
    const int t  = threadIdx.x;
    float v = d_gdot[bn*Mm + t] * boundary[b*Mm + t] * bweights[b*Mm + t];
#pragma unroll
    for (int o = 16; o > 0; o >>= 1) v += __shfl_down_sync(0xffffffffu, v, o);
    if ((t & 31) == 0) s2[t >> 5] = v;
    __syncthreads();
    if (t == 0) out[bn] = s2[0] + s2[1];
}

// =====================================================================
extern "C" void kernel_launch(void* const* d_in, const int* in_sizes, int n_in,
                              void* d_out, int out_size)
{
    const float* phase    = (const float*)d_in[0];
    const float* bcoords  = (const float*)d_in[1];
    const float* boundary = (const float*)d_in[2];
    const float* bweights = (const float*)d_in[3];
    const float* posc     = (const float*)d_in[4];
    const float* sigma    = (const float*)d_in[5];
    const float* velc     = (const float*)d_in[6];
    const float* vwt      = (const float*)d_in[7];
    const float* scat     = (const float*)d_in[8];
    const float* sscat    = (const float*)d_in[9];
    const float* aw0 = (const float*)d_in[10];
    const float* ab0 = (const float*)d_in[11];
    const float* aw1 = (const float*)d_in[12];
    const float* ab1 = (const float*)d_in[13];
    const float* aw2 = (const float*)d_in[14];
    const float* ab2 = (const float*)d_in[15];
    const float* tw0 = (const float*)d_in[16];
    const float* tb0 = (const float*)d_in[17];
    const float* tw1 = (const float*)d_in[18];
    const float* tb1 = (const float*)d_in[19];
    const float* tw2 = (const float*)d_in[20];
    const float* tb2 = (const float*)d_in[21];
    const float* sw0 = (const float*)d_in[22];
    const float* sb0 = (const float*)d_in[23];
    const float* sw1 = (const float*)d_in[24];
    const float* sb1 = (const float*)d_in[25];
    const float* ow  = (const float*)d_in[26];
    float* out = (float*)d_out;

    k_dup<<<128, 256>>>(tw1, tw2, sw0, sw1);
    k1_attn<<<Bb*Nn*K1, 128>>>(phase, posc, sigma, velc,
                               aw0, ab0, aw1, ab1, aw2, ab2, tw0, tb0);
    k_bm<<<Bb*Mm, TWd>>>(bcoords, tw0);
    k4_main<<<Bb*Nn*(Mm/2), 128>>>(
        scat, sscat, vwt, tb1, tb2, sb0, sb1, ow);
    k6_final<<<Bb*Nn, 64>>>(boundary, bweights, out);
}